// round 4
// baseline (speedup 1.0000x reference)
#include <cuda_runtime.h>
#include <cstdint>
#include <math.h>

#define TOKENS 36864
#define PS 768
#define HID 1536

#define BM 128
#define BN 128
#define BKF 16            // K floats per pipeline stage
#define NST 4             // stages
#define ROWF 20           // padded smem row length in floats (bank-conflict-free)
#define STAGE_FLOATS (2 * 128 * ROWF)         // A tile + B tile (5120 floats)
#define SMEM_BYTES (NST * STAGE_FLOATS * 4)   // 81920

// Scratch (device globals — allocation guards forbid cudaMalloc)
__device__ float g_Y[(size_t)TOKENS * PS];     // LN'd patches, tf32-rounded
__device__ float g_H[(size_t)TOKENS * HID];    // hidden acts, tf32-rounded
__device__ float g_W1T[(size_t)HID * PS];      // w1^T [1536,768] K-major, tf32-rounded
__device__ float g_W2T[(size_t)PS * HID];      // w2^T [768,1536] K-major, tf32-rounded

// ---------------------------------------------------------------------------
__device__ __forceinline__ float to_tf32(float x) {
    uint32_t o;
    asm("cvt.rna.tf32.f32 %0, %1;" : "=r"(o) : "f"(x));
    return __uint_as_float(o);
}
__device__ __forceinline__ void cp_async16(uint32_t dst, const void* src) {
    asm volatile("cp.async.cg.shared.global [%0], [%1], 16;\n" :: "r"(dst), "l"(src));
}
__device__ __forceinline__ uint32_t smem_u32(const void* p) {
    uint32_t a;
    asm("{ .reg .u64 t; cvta.to.shared.u64 t, %1; cvt.u32.u64 %0, t; }" : "=r"(a) : "l"(p));
    return a;
}
__device__ __forceinline__ void cp_commit() { asm volatile("cp.async.commit_group;\n" ::: "memory"); }
__device__ __forceinline__ void cp_wait2()  { asm volatile("cp.async.wait_group 2;\n" ::: "memory"); }
__device__ __forceinline__ void cp_wait1()  { asm volatile("cp.async.wait_group 1;\n" ::: "memory"); }
__device__ __forceinline__ void cp_wait0()  { asm volatile("cp.async.wait_group 0;\n" ::: "memory"); }

__device__ __forceinline__ void mma_tf32(float* d, const uint32_t* a, const uint32_t* b) {
    asm volatile(
        "mma.sync.aligned.m16n8k8.row.col.f32.tf32.tf32.f32 "
        "{%0,%1,%2,%3}, {%4,%5,%6,%7}, {%8,%9}, {%0,%1,%2,%3};"
        : "+f"(d[0]), "+f"(d[1]), "+f"(d[2]), "+f"(d[3])
        : "r"(a[0]), "r"(a[1]), "r"(a[2]), "r"(a[3]), "r"(b[0]), "r"(b[1]));
}

// ---------------------------------------------------------------------------
// Kernel 1: unfold (patchify) + LayerNorm, output tf32-rounded
// ---------------------------------------------------------------------------
__global__ void patch_ln_kernel(const float* __restrict__ x,
                                const float* __restrict__ ln_w,
                                const float* __restrict__ ln_b) {
    const int token = blockIdx.x;
    const int b  = token / 576;
    const int l  = token - b * 576;
    const int hp = l / 24;
    const int wp = l - hp * 24;
    const int t  = threadIdx.x;

    float v[3];
#pragma unroll
    for (int i = 0; i < 3; ++i) {
        const int p   = t + i * 256;
        const int c   = p >> 8;
        const int rem = p & 255;
        const int ph  = rem >> 4;
        const int pw  = rem & 15;
        const int xi  = ((b * 3 + c) * 384 + hp * 16 + ph) * 384 + wp * 16 + pw;
        v[i] = x[xi];
    }
    float s  = v[0] + v[1] + v[2];
    float sq = v[0] * v[0] + v[1] * v[1] + v[2] * v[2];
#pragma unroll
    for (int o = 16; o > 0; o >>= 1) {
        s  += __shfl_xor_sync(0xffffffffu, s, o);
        sq += __shfl_xor_sync(0xffffffffu, sq, o);
    }
    __shared__ float red_s[8], red_q[8];
    const int warp = t >> 5, lane = t & 31;
    if (lane == 0) { red_s[warp] = s; red_q[warp] = sq; }
    __syncthreads();
    float tot = 0.f, totq = 0.f;
#pragma unroll
    for (int i = 0; i < 8; ++i) { tot += red_s[i]; totq += red_q[i]; }
    const float mu  = tot * (1.0f / 768.0f);
    const float var = totq * (1.0f / 768.0f) - mu * mu;
    const float inv = rsqrtf(var + 1e-5f);

    float* yrow = g_Y + (size_t)token * PS;
#pragma unroll
    for (int i = 0; i < 3; ++i) {
        const int p = t + i * 256;
        yrow[p] = to_tf32((v[i] - mu) * inv * ln_w[p] + ln_b[p]);
    }
}

// ---------------------------------------------------------------------------
// Weight transpose: src [R,C] row-major -> DST (device symbol) [C,R], tf32-rounded
// ---------------------------------------------------------------------------
template <int WHICH>
__global__ void transpose_kernel(const float* __restrict__ src, int R, int C) {
    float* __restrict__ dst = (WHICH == 0) ? g_W1T : g_W2T;
    __shared__ float t[32][33];
    const int bx = blockIdx.x * 32, by = blockIdx.y * 32;
    const int x = threadIdx.x, y = threadIdx.y;
#pragma unroll
    for (int i = 0; i < 32; i += 8)
        t[y + i][x] = src[(size_t)(by + y + i) * C + bx + x];
    __syncthreads();
#pragma unroll
    for (int i = 0; i < 32; i += 8)
        dst[(size_t)(bx + y + i) * R + by + x] = to_tf32(t[x][y + i]);
}

// ---------------------------------------------------------------------------
// TF32 mma.sync GEMM: C[M,NGL] = A[M,K] * Bt[NGL,K]^T, CTA 128x128, 8 warps,
// warp tile 64x32, mma m16n8k8. 4-stage cp.async, reg-fragment double buffer.
// EPI 0: C = tf32(gelu(C + bias)) -> g_H
// EPI 1: C = C + bias, fold + residual x -> out
// ---------------------------------------------------------------------------
template <int NGL, int K, int EPI>
__global__ __launch_bounds__(256, 2) void mma_gemm_kernel(
        const float* __restrict__ bias,
        const float* __restrict__ x,
        float* __restrict__ out) {
    extern __shared__ float smem[];
    const float* __restrict__ A  = (EPI == 0) ? g_Y : g_H;
    const float* __restrict__ Bt = (EPI == 0) ? g_W1T : g_W2T;

    const int tid  = threadIdx.x;
    const int lane = tid & 31;
    const int wid  = tid >> 5;
    const int wm   = wid & 1;        // warp row (0..1) -> 64 rows
    const int wn   = wid >> 1;       // warp col (0..3) -> 32 cols
    const int g    = lane >> 2;      // group id 0..7
    const int tig  = lane & 3;       // thread in group
    const int mBase = blockIdx.y * BM;
    const int nBase = blockIdx.x * BN;

    const uint32_t sbase = smem_u32(smem);

    // cp.async geometry: 512 A-chunks + 512 B-chunks of 16B per stage; 4/thread
    const int r0 = tid >> 2;
    const int s0 = tid & 3;
    const int r1 = (tid + 256) >> 2;
    const float* gA0 = A  + (size_t)(mBase + r0) * K + s0 * 4;
    const float* gA1 = A  + (size_t)(mBase + r1) * K + s0 * 4;
    const float* gB0 = Bt + (size_t)(nBase + r0) * K + s0 * 4;
    const float* gB1 = Bt + (size_t)(nBase + r1) * K + s0 * 4;
    const uint32_t dA0 = (uint32_t)(r0 * ROWF + s0 * 4) * 4;
    const uint32_t dA1 = (uint32_t)(r1 * ROWF + s0 * 4) * 4;
    const uint32_t dB0 = dA0 + 128 * ROWF * 4;
    const uint32_t dB1 = dA1 + 128 * ROWF * 4;

    auto load_stage = [&](int slot, int ks) {
        const uint32_t sb = sbase + (uint32_t)slot * STAGE_FLOATS * 4;
        const int ko = ks * BKF;
        cp_async16(sb + dA0, gA0 + ko);
        cp_async16(sb + dA1, gA1 + ko);
        cp_async16(sb + dB0, gB0 + ko);
        cp_async16(sb + dB1, gB1 + ko);
        cp_commit();
    };

    // fragment base offsets (float index within a stage)
    const int aoff = (wm * 64 + g) * ROWF + tig;
    const int boff = 128 * ROWF + (wn * 32 + g) * ROWF + tig;

    float acc[4][4][4];
#pragma unroll
    for (int i = 0; i < 4; ++i)
#pragma unroll
        for (int j = 0; j < 4; ++j)
#pragma unroll
            for (int q = 0; q < 4; ++q) acc[i][j][q] = 0.f;

    uint32_t afr[2][4][4];
    uint32_t bfr[4][2];

    auto frag_a = [&](uint32_t fr[4][4], int slot, int kk) {
        const float* p = smem + slot * STAGE_FLOATS + aoff + kk * 8;
#pragma unroll
        for (int mt = 0; mt < 4; ++mt) {
            fr[mt][0] = __float_as_uint(p[(mt * 16) * ROWF]);
            fr[mt][1] = __float_as_uint(p[(mt * 16 + 8) * ROWF]);
            fr[mt][2] = __float_as_uint(p[(mt * 16) * ROWF + 4]);
            fr[mt][3] = __float_as_uint(p[(mt * 16 + 8) * ROWF + 4]);
        }
    };
    auto frag_b = [&](int slot, int kk) {
        const float* p = smem + slot * STAGE_FLOATS + boff + kk * 8;
#pragma unroll
        for (int nt = 0; nt < 4; ++nt) {
            bfr[nt][0] = __float_as_uint(p[(nt * 8) * ROWF]);
            bfr[nt][1] = __float_as_uint(p[(nt * 8) * ROWF + 4]);
        }
    };
    auto mma_set = [&](uint32_t fa[4][4]) {
#pragma unroll
        for (int mt = 0; mt < 4; ++mt)
#pragma unroll
            for (int nt = 0; nt < 4; ++nt)
                mma_tf32(acc[mt][nt], fa[mt], bfr[nt]);
    };

    constexpr int KT = K / BKF;
    load_stage(0, 0);
    load_stage(1, 1);
    load_stage(2, 2);
    load_stage(3, 3);
    cp_wait2();
    __syncthreads();
    frag_a(afr[0], 0, 0);

    for (int kt = 0; kt < KT; ++kt) {
        const int slot = kt & 3;
        frag_b(slot, 0);
        frag_a(afr[1], slot, 1);
        mma_set(afr[0]);
        frag_b(slot, 1);
        if (kt + 1 < KT) {
            if (kt + 4 <= KT) cp_wait2();
            else if (kt + 3 <= KT) cp_wait1();
            else cp_wait0();
            __syncthreads();
            if (kt + 4 < KT) load_stage((kt + 4) & 3, kt + 4);
            frag_a(afr[0], (kt + 1) & 3, 0);
        }
        mma_set(afr[1]);
    }

    // ---------------- epilogue ----------------
#pragma unroll
    for (int mt = 0; mt < 4; ++mt) {
#pragma unroll
        for (int half = 0; half < 2; ++half) {
            const int row = mBase + wm * 64 + mt * 16 + g + half * 8;
            int bimg = 0, hp = 0, wp = 0;
            if (EPI == 1) {
                bimg = row / 576;
                const int l = row - bimg * 576;
                hp = l / 24;
                wp = l - hp * 24;
            }
#pragma unroll
            for (int nt = 0; nt < 4; ++nt) {
                const int col = nBase + wn * 32 + nt * 8 + 2 * tig;
                const float c0 = acc[mt][nt][half * 2 + 0];
                const float c1 = acc[mt][nt][half * 2 + 1];
                if (EPI == 0) {
                    float a0 = c0 + __ldg(&bias[col]);
                    float a1 = c1 + __ldg(&bias[col + 1]);
                    a0 = 0.5f * a0 * (1.0f + erff(a0 * 0.70710678118654752f));
                    a1 = 0.5f * a1 * (1.0f + erff(a1 * 0.70710678118654752f));
                    float2 v = make_float2(to_tf32(a0), to_tf32(a1));
                    *(float2*)(g_H + (size_t)row * NGL + col) = v;
                } else {
                    const int cg  = col >> 8;
                    const int rem = col & 255;
                    const int ph  = rem >> 4;
                    const int pw  = rem & 15;
                    const size_t oi = (((size_t)(bimg * 3 + cg) * 384 + hp * 16 + ph) * 384
                                       + wp * 16 + pw);
                    const float2 xv = *(const float2*)(x + oi);
                    float2 v;
                    v.x = xv.x + c0 + __ldg(&bias[col]);
                    v.y = xv.y + c1 + __ldg(&bias[col + 1]);
                    *(float2*)(out + oi) = v;
                }
            }
        }
    }
}

extern "C" void kernel_launch(void* const* d_in, const int* in_sizes, int n_in,
                              void* d_out, int out_size) {
    const float* x    = (const float*)d_in[0];
    const float* ln_w = (const float*)d_in[1];
    const float* ln_b = (const float*)d_in[2];
    const float* w1   = (const float*)d_in[3];
    const float* b1   = (const float*)d_in[4];
    const float* w2   = (const float*)d_in[5];
    const float* b2   = (const float*)d_in[6];
    float* out        = (float*)d_out;

    static bool configured = false;
    if (!configured) {
        cudaFuncSetAttribute(mma_gemm_kernel<HID, PS, 0>,
                             cudaFuncAttributeMaxDynamicSharedMemorySize, SMEM_BYTES);
        cudaFuncSetAttribute(mma_gemm_kernel<PS, HID, 1>,
                             cudaFuncAttributeMaxDynamicSharedMemorySize, SMEM_BYTES);
        configured = true;
    }

    dim3 tb(32, 8);
    transpose_kernel<0><<<dim3(HID / 32, PS / 32), tb>>>(w1, PS, HID);
    transpose_kernel<1><<<dim3(PS / 32, HID / 32), tb>>>(w2, HID, PS);

    patch_ln_kernel<<<TOKENS, 256>>>(x, ln_w, ln_b);

    dim3 g1(HID / BN, TOKENS / BM);   // (12, 288)
    mma_gemm_kernel<HID, PS, 0><<<g1, 256, SMEM_BYTES>>>(b1, nullptr, nullptr);

    dim3 g2(PS / BN, TOKENS / BM);    // (6, 288)
    mma_gemm_kernel<PS, HID, 1><<<g2, 256, SMEM_BYTES>>>(b2, x, out);
}

// round 5
// speedup vs baseline: 1.2275x; 1.2275x over previous
#include <cuda_runtime.h>
#include <cstdint>
#include <math.h>

#define TOKENS 36864
#define PS 768
#define HID 1536

#define BM 128
#define BN 128
#define BKF 32                 // K floats per pipeline stage
#define ROWF 40                // padded smem row floats (32 data + 8 pad), LDS.64 conflict-free
#define STAGE_FLOATS (2 * 128 * ROWF)         // 10240 floats = 40KB
#define SMEM_BYTES (2 * STAGE_FLOATS * 4)     // 81920 (2 stages)

// Scratch (device globals — allocation guards forbid cudaMalloc)
__device__ float g_Y[(size_t)TOKENS * PS];     // LN'd patches, tf32, k-permuted
__device__ float g_H[(size_t)TOKENS * HID];    // hidden acts, tf32, k-permuted
__device__ float g_W1T[(size_t)HID * PS];      // w1^T [1536,768], k(=PS)-permuted
__device__ float g_W2T[(size_t)PS * HID];      // w2^T [768,1536], k(=HID)-permuted

// k-permutation within 8-groups: logical k -> physical position
__device__ __forceinline__ int permk(int k) {
    return (k & ~7) | (((k & 3) << 1) | ((k >> 2) & 1));
}
__device__ __forceinline__ float to_tf32(float x) {
    uint32_t o;
    asm("cvt.rna.tf32.f32 %0, %1;" : "=r"(o) : "f"(x));
    return __uint_as_float(o);
}
__device__ __forceinline__ uint32_t smem_u32(const void* p) {
    uint32_t a;
    asm("{ .reg .u64 t; cvta.to.shared.u64 t, %1; cvt.u32.u64 %0, t; }" : "=r"(a) : "l"(p));
    return a;
}
__device__ __forceinline__ void cp_async16(uint32_t dst, const void* src) {
    asm volatile("cp.async.cg.shared.global [%0], [%1], 16;\n" :: "r"(dst), "l"(src));
}
__device__ __forceinline__ void cp_commit() { asm volatile("cp.async.commit_group;\n" ::: "memory"); }
__device__ __forceinline__ void cp_wait0()  { asm volatile("cp.async.wait_group 0;\n" ::: "memory"); }

__device__ __forceinline__ void mma_tf32(float* d, const uint32_t* a, const uint32_t* b) {
    asm volatile(
        "mma.sync.aligned.m16n8k8.row.col.f32.tf32.tf32.f32 "
        "{%0,%1,%2,%3}, {%4,%5,%6,%7}, {%8,%9}, {%0,%1,%2,%3};"
        : "+f"(d[0]), "+f"(d[1]), "+f"(d[2]), "+f"(d[3])
        : "r"(a[0]), "r"(a[1]), "r"(a[2]), "r"(a[3]), "r"(b[0]), "r"(b[1]));
}

// ---------------------------------------------------------------------------
// Kernel 1: unfold + LayerNorm, tf32-rounded, k-permuted output
// ---------------------------------------------------------------------------
__global__ void patch_ln_kernel(const float* __restrict__ x,
                                const float* __restrict__ ln_w,
                                const float* __restrict__ ln_b) {
    const int token = blockIdx.x;
    const int b  = token / 576;
    const int l  = token - b * 576;
    const int hp = l / 24;
    const int wp = l - hp * 24;
    const int t  = threadIdx.x;

    float v[3];
#pragma unroll
    for (int i = 0; i < 3; ++i) {
        const int p   = t + i * 256;
        const int c   = p >> 8;
        const int rem = p & 255;
        const int ph  = rem >> 4;
        const int pw  = rem & 15;
        const int xi  = ((b * 3 + c) * 384 + hp * 16 + ph) * 384 + wp * 16 + pw;
        v[i] = x[xi];
    }
    float s  = v[0] + v[1] + v[2];
    float sq = v[0] * v[0] + v[1] * v[1] + v[2] * v[2];
#pragma unroll
    for (int o = 16; o > 0; o >>= 1) {
        s  += __shfl_xor_sync(0xffffffffu, s, o);
        sq += __shfl_xor_sync(0xffffffffu, sq, o);
    }
    __shared__ float red_s[8], red_q[8];
    const int warp = t >> 5, lane = t & 31;
    if (lane == 0) { red_s[warp] = s; red_q[warp] = sq; }
    __syncthreads();
    float tot = 0.f, totq = 0.f;
#pragma unroll
    for (int i = 0; i < 8; ++i) { tot += red_s[i]; totq += red_q[i]; }
    const float mu  = tot * (1.0f / 768.0f);
    const float var = totq * (1.0f / 768.0f) - mu * mu;
    const float inv = rsqrtf(var + 1e-5f);

    float* yrow = g_Y + (size_t)token * PS;
#pragma unroll
    for (int i = 0; i < 3; ++i) {
        const int p = t + i * 256;
        yrow[permk(p)] = to_tf32((v[i] - mu) * inv * ln_w[p] + ln_b[p]);
    }
}

// ---------------------------------------------------------------------------
// Transpose: src [R,C] -> dst [C,R], column index (K dim) permuted, tf32.
// ---------------------------------------------------------------------------
template <int WHICH>
__global__ void transpose_kernel(const float* __restrict__ src, int R, int C) {
    float* __restrict__ dst = (WHICH == 0) ? g_W1T : g_W2T;
    __shared__ float t[32][33];
    const int bx = blockIdx.x * 32, by = blockIdx.y * 32;
    const int x = threadIdx.x, y = threadIdx.y;
#pragma unroll
    for (int i = 0; i < 32; i += 8)
        t[y + i][x] = src[(size_t)(by + y + i) * C + bx + x];
    __syncthreads();
#pragma unroll
    for (int i = 0; i < 32; i += 8)
        dst[(size_t)(bx + y + i) * R + permk(by + x)] = to_tf32(t[x][y + i]);
}

// ---------------------------------------------------------------------------
// TF32 mma.sync GEMM: C[M,NGL] = A[M,K]*Bt[NGL,K]^T, CTA 128x128, 8 warps,
// warp tile 64x32. BK=32 double-buffered cp.async, LDS.64 fragments.
// EPI 0: C = tf32(gelu(C+bias)) -> g_H (columns stored k-permuted)
// EPI 1: C = C+bias, fold + residual x -> out
// ---------------------------------------------------------------------------
template <int NGL, int K, int EPI>
__global__ __launch_bounds__(256, 2) void mma_gemm_kernel(
        const float* __restrict__ bias,
        const float* __restrict__ x,
        float* __restrict__ out) {
    extern __shared__ float smem[];
    const float* __restrict__ A  = (EPI == 0) ? g_Y : g_H;
    const float* __restrict__ Bt = (EPI == 0) ? g_W1T : g_W2T;

    const int tid  = threadIdx.x;
    const int lane = tid & 31;
    const int wid  = tid >> 5;
    const int wm   = wid & 1;
    const int wn   = wid >> 1;
    const int g    = lane >> 2;
    const int tig  = lane & 3;
    const int mBase = blockIdx.y * BM;
    const int nBase = blockIdx.x * BN;

    const uint32_t sbase = smem_u32(smem);

    // cp.async geometry: 1024 A + 1024 B 16B-chunks per stage, 8 per thread.
    const int r0 = tid >> 3;          // base row 0..31
    const int j0 = tid & 7;           // 16B chunk within 128B row
    const float* gA0 = A  + (size_t)(mBase + r0) * K + j0 * 4;
    const float* gB0 = Bt + (size_t)(nBase + r0) * K + j0 * 4;
    const uint32_t dA0 = (uint32_t)r0 * 160u + (uint32_t)j0 * 16u;

    auto load_stage = [&](int slot, int ks) {
        const uint32_t sb = sbase + (uint32_t)slot * (STAGE_FLOATS * 4);
        const int ko = ks * BKF;
#pragma unroll
        for (int i = 0; i < 4; ++i)
            cp_async16(sb + dA0 + i * (32u * 160u), gA0 + (size_t)(32 * i) * K + ko);
#pragma unroll
        for (int i = 0; i < 4; ++i)
            cp_async16(sb + 128u * 160u + dA0 + i * (32u * 160u), gB0 + (size_t)(32 * i) * K + ko);
        cp_commit();
    };

    float acc[4][4][4];
#pragma unroll
    for (int i = 0; i < 4; ++i)
#pragma unroll
        for (int j = 0; j < 4; ++j)
#pragma unroll
            for (int q = 0; q < 4; ++q) acc[i][j][q] = 0.f;

    const int aoff = (wm * 64 + g) * ROWF + 2 * tig;
    const int boff = 128 * ROWF + (wn * 32 + g) * ROWF + 2 * tig;

    constexpr int KT = K / BKF;
    load_stage(0, 0);

    for (int kt = 0; kt < KT; ++kt) {
        cp_wait0();
        __syncthreads();
        if (kt + 1 < KT) load_stage((kt + 1) & 1, kt + 1);

        const float* st = smem + (kt & 1) * STAGE_FLOATS;
        const float* sa = st + aoff;
        const float* sb = st + boff;
#pragma unroll
        for (int kk = 0; kk < 4; ++kk) {
            uint32_t afr[4][4], bfr[4][2];
            const int kc = kk * 8;
#pragma unroll
            for (int mt = 0; mt < 4; ++mt) {
                const float2 lo = *(const float2*)(sa + (mt * 16) * ROWF + kc);
                const float2 hi = *(const float2*)(sa + (mt * 16 + 8) * ROWF + kc);
                afr[mt][0] = __float_as_uint(lo.x);
                afr[mt][1] = __float_as_uint(hi.x);
                afr[mt][2] = __float_as_uint(lo.y);
                afr[mt][3] = __float_as_uint(hi.y);
            }
#pragma unroll
            for (int nt = 0; nt < 4; ++nt) {
                const float2 v = *(const float2*)(sb + (nt * 8) * ROWF + kc);
                bfr[nt][0] = __float_as_uint(v.x);
                bfr[nt][1] = __float_as_uint(v.y);
            }
#pragma unroll
            for (int mt = 0; mt < 4; ++mt)
#pragma unroll
                for (int nt = 0; nt < 4; ++nt)
                    mma_tf32(acc[mt][nt], afr[mt], bfr[nt]);
        }
    }

    // ---------------- epilogue ----------------
#pragma unroll
    for (int mt = 0; mt < 4; ++mt) {
#pragma unroll
        for (int half = 0; half < 2; ++half) {
            const int row = mBase + wm * 64 + mt * 16 + g + half * 8;
            int bimg = 0, hp = 0, wp = 0;
            if (EPI == 1) {
                bimg = row / 576;
                const int l = row - bimg * 576;
                hp = l / 24;
                wp = l - hp * 24;
            }
#pragma unroll
            for (int nt = 0; nt < 4; ++nt) {
                const int col = nBase + wn * 32 + nt * 8 + 2 * tig;  // logical
                const float c0 = acc[mt][nt][half * 2 + 0];
                const float c1 = acc[mt][nt][half * 2 + 1];
                if (EPI == 0) {
                    float a0 = c0 + __ldg(&bias[col]);
                    float a1 = c1 + __ldg(&bias[col + 1]);
                    a0 = 0.5f * a0 * (1.0f + erff(a0 * 0.70710678118654752f));
                    a1 = 0.5f * a1 * (1.0f + erff(a1 * 0.70710678118654752f));
                    float* hrow = g_H + (size_t)row * NGL;
                    hrow[permk(col)]     = to_tf32(a0);
                    hrow[permk(col + 1)] = to_tf32(a1);
                } else {
                    const int cg  = col >> 8;
                    const int rem = col & 255;
                    const int ph  = rem >> 4;
                    const int pw  = rem & 15;
                    const size_t oi = (((size_t)(bimg * 3 + cg) * 384 + hp * 16 + ph) * 384
                                       + wp * 16 + pw);
                    const float2 xv = *(const float2*)(x + oi);
                    float2 v;
                    v.x = xv.x + c0 + __ldg(&bias[col]);
                    v.y = xv.y + c1 + __ldg(&bias[col + 1]);
                    *(float2*)(out + oi) = v;
                }
            }
        }
    }
}

extern "C" void kernel_launch(void* const* d_in, const int* in_sizes, int n_in,
                              void* d_out, int out_size) {
    const float* x    = (const float*)d_in[0];
    const float* ln_w = (const float*)d_in[1];
    const float* ln_b = (const float*)d_in[2];
    const float* w1   = (const float*)d_in[3];
    const float* b1   = (const float*)d_in[4];
    const float* w2   = (const float*)d_in[5];
    const float* b2   = (const float*)d_in[6];
    float* out        = (float*)d_out;

    static bool configured = false;
    if (!configured) {
        cudaFuncSetAttribute(mma_gemm_kernel<HID, PS, 0>,
                             cudaFuncAttributeMaxDynamicSharedMemorySize, SMEM_BYTES);
        cudaFuncSetAttribute(mma_gemm_kernel<PS, HID, 1>,
                             cudaFuncAttributeMaxDynamicSharedMemorySize, SMEM_BYTES);
        configured = true;
    }

    dim3 tb(32, 8);
    transpose_kernel<0><<<dim3(HID / 32, PS / 32), tb>>>(w1, PS, HID);
    transpose_kernel<1><<<dim3(PS / 32, HID / 32), tb>>>(w2, HID, PS);

    patch_ln_kernel<<<TOKENS, 256>>>(x, ln_w, ln_b);

    dim3 g1(HID / BN, TOKENS / BM);   // (12, 288)
    mma_gemm_kernel<HID, PS, 0><<<g1, 256, SMEM_BYTES>>>(b1, nullptr, nullptr);

    dim3 g2(PS / BN, TOKENS / BM);    // (6, 288)
    mma_gemm_kernel<PS, HID, 1><<<g2, 256, SMEM_BYTES>>>(b2, x, out);
}